// round 1
// baseline (speedup 1.0000x reference)
#include <cuda_runtime.h>

// Problem constants (fixed by the dataset)
#define BB 8
#define NXX 512
#define NRR 512
#define DD 256
#define HH 256

// Scratch (no cudaMalloc allowed)
__device__ float g_hX[BB * NXX * HH];       // [b, x, h]
__device__ float g_hR[BB * NRR * HH];       // [b, r, h]
__device__ float g_S[BB * NXX * NRR];       // [b, x, r]
__device__ float g_attn[BB * NXX * NRR];    // [b, x, r]

// ---------------------------------------------------------------------------
// Kernel 1: projection GEMM  out[n,h] = sum_d A[n,d] * W[h,d] + bias[h]
// A: [M=4096, 256], W: [256, 256], 64x64 tile, 256 threads, 4x4 per thread.
// ---------------------------------------------------------------------------
__global__ __launch_bounds__(256) void proj_kernel(
    const float* __restrict__ A, const float* __restrict__ W,
    const float* __restrict__ bias, float* __restrict__ out)
{
    __shared__ float As[16][64];
    __shared__ float Ws[16][64];
    const int tid = threadIdx.x;
    const int tx = tid & 15;        // n-dim
    const int ty = tid >> 4;        // m-dim
    const int m0 = blockIdx.x * 64;
    const int n0 = blockIdx.y * 64;

    float acc[4][4] = {};

    const int lr = tid >> 2;              // 0..63 row within tile
    const int lk = (tid & 3) << 2;        // 0,4,8,12 within k-chunk

    for (int kc = 0; kc < DD; kc += 16) {
        float4 va = *(const float4*)&A[(m0 + lr) * DD + kc + lk];
        float4 vw = *(const float4*)&W[(n0 + lr) * DD + kc + lk];
        As[lk + 0][lr] = va.x; As[lk + 1][lr] = va.y;
        As[lk + 2][lr] = va.z; As[lk + 3][lr] = va.w;
        Ws[lk + 0][lr] = vw.x; Ws[lk + 1][lr] = vw.y;
        Ws[lk + 2][lr] = vw.z; Ws[lk + 3][lr] = vw.w;
        __syncthreads();
#pragma unroll
        for (int k = 0; k < 16; k++) {
            float4 a = *(const float4*)&As[k][ty << 2];
            float4 w = *(const float4*)&Ws[k][tx << 2];
            float av[4] = {a.x, a.y, a.z, a.w};
            float wv[4] = {w.x, w.y, w.z, w.w};
#pragma unroll
            for (int i = 0; i < 4; i++)
#pragma unroll
                for (int j = 0; j < 4; j++)
                    acc[i][j] = fmaf(av[i], wv[j], acc[i][j]);
        }
        __syncthreads();
    }

    float4 bv = *(const float4*)&bias[n0 + (tx << 2)];
#pragma unroll
    for (int i = 0; i < 4; i++) {
        float4 o;
        o.x = acc[i][0] + bv.x; o.y = acc[i][1] + bv.y;
        o.z = acc[i][2] + bv.z; o.w = acc[i][3] + bv.w;
        *(float4*)&out[(m0 + (ty << 2) + i) * HH + n0 + (tx << 2)] = o;
    }
}

// ---------------------------------------------------------------------------
// Kernel 2: scores  S[b,x,r] = sum_h tanh(hX[b,x,h] + hR[b,r,h]) * v[h] + vb
// Block = (32 x) x (32 r) tile; H processed in two chunks of 128.
// Thread map: lane lr = r, warp w -> x in {4w..4w+3}. MUFU (tanh) bound.
// ---------------------------------------------------------------------------
__global__ __launch_bounds__(256) void score_kernel(
    const float* __restrict__ hX, const float* __restrict__ hR,
    const float* __restrict__ vw, const float* __restrict__ vb,
    float* __restrict__ S)
{
    __shared__ float hXs[32][128];     // row-major: broadcast reads per warp
    __shared__ float hRt[128][33];     // transposed + pad: conflict-free by lane
    __shared__ float v_s[HH];

    const int xt = blockIdx.x, rt = blockIdx.y, b = blockIdx.z;
    const int x0 = xt * 32, r0 = rt * 32;
    const int tid = threadIdx.x;
    const int lr = tid & 31;           // r lane
    const int w  = tid >> 5;           // warp -> x group

    v_s[tid] = vw[tid];

    const float* hXb = hX + (size_t)(b * NXX + x0) * HH;
    const float* hRb = hR + (size_t)(b * NRR + r0) * HH;

    float acc[4] = {0.f, 0.f, 0.f, 0.f};

    for (int hc = 0; hc < 2; hc++) {
        __syncthreads();
        // load hX tile (row-major), 32x128 floats
        for (int i = tid; i < 32 * 32; i += 256) {
            int row = i >> 5, c4 = (i & 31) << 2;
            *(float4*)&hXs[row][c4] =
                *(const float4*)&hXb[row * HH + hc * 128 + c4];
        }
        // load hR tile transposed
        for (int i = tid; i < 32 * 32; i += 256) {
            int row = i >> 5, c4 = (i & 31) << 2;
            float4 v = *(const float4*)&hRb[row * HH + hc * 128 + c4];
            hRt[c4 + 0][row] = v.x; hRt[c4 + 1][row] = v.y;
            hRt[c4 + 2][row] = v.z; hRt[c4 + 3][row] = v.w;
        }
        __syncthreads();

        const float* vv = &v_s[hc * 128];
#pragma unroll 4
        for (int h = 0; h < 128; h++) {
            float hr = hRt[h][lr];
            float vh = vv[h];
#pragma unroll
            for (int j = 0; j < 4; j++) {
                float t = hXs[(w << 2) + j][h] + hr;
                float th;
                asm("tanh.approx.f32 %0, %1;" : "=f"(th) : "f"(t));
                acc[j] = fmaf(th, vh, acc[j]);
            }
        }
    }

    const float vbv = vb[0];
#pragma unroll
    for (int j = 0; j < 4; j++) {
        int x = x0 + (w << 2) + j;
        S[((size_t)b * NXX + x) * NRR + r0 + lr] = acc[j] + vbv;
    }
}

// ---------------------------------------------------------------------------
// Kernel 3: softmax over x (dim 1).  Block handles (b, 32 r's), coalesced.
// ---------------------------------------------------------------------------
__global__ __launch_bounds__(256) void softmax_kernel(
    const float* __restrict__ S, float* __restrict__ attn)
{
    const int r0 = blockIdx.x * 32;
    const int b  = blockIdx.y;
    const int tid = threadIdx.x;
    const int tr = tid & 31;       // r lane
    const int tg = tid >> 5;       // x group (8 groups of 64)

    __shared__ float red[8][32];

    const float* Sb = S + (size_t)b * NXX * NRR + r0;
    float* Ab = attn + (size_t)b * NXX * NRR + r0;

    float m = -1e30f;
    for (int x = tg * 64; x < tg * 64 + 64; x++)
        m = fmaxf(m, Sb[(size_t)x * NRR + tr]);
    red[tg][tr] = m;
    __syncthreads();
    if (tg == 0) {
        float mm = red[0][tr];
#pragma unroll
        for (int i = 1; i < 8; i++) mm = fmaxf(mm, red[i][tr]);
        red[0][tr] = mm;
    }
    __syncthreads();
    const float M = red[0][tr];
    __syncthreads();

    float s = 0.f;
    for (int x = tg * 64; x < tg * 64 + 64; x++)
        s += __expf(Sb[(size_t)x * NRR + tr] - M);
    red[tg][tr] = s;
    __syncthreads();
    if (tg == 0) {
        float ss = red[0][tr];
#pragma unroll
        for (int i = 1; i < 8; i++) ss += red[i][tr];
        red[0][tr] = ss;
    }
    __syncthreads();
    const float inv = 1.0f / red[0][tr];

    for (int x = tg * 64; x < tg * 64 + 64; x++)
        Ab[(size_t)x * NRR + tr] = __expf(Sb[(size_t)x * NRR + tr] - M) * inv;
}

// ---------------------------------------------------------------------------
// Kernel 4: out[b,r,e] = sum_x attn[b,x,r] * X[b,x,e]
// Both operands k(x)-major; 64x64 tile, 4x4 per thread.
// ---------------------------------------------------------------------------
__global__ __launch_bounds__(256) void outgemm_kernel(
    const float* __restrict__ attn, const float* __restrict__ X,
    float* __restrict__ out)
{
    __shared__ float As[16][64];   // attn[k][r]
    __shared__ float Xs[16][64];   // X[k][e]
    const int r0 = blockIdx.x * 64;
    const int e0 = blockIdx.y * 64;
    const int b  = blockIdx.z;
    const int tid = threadIdx.x;
    const int tx = tid & 15;       // e
    const int ty = tid >> 4;       // r

    const float* Ab = attn + (size_t)b * NXX * NRR;
    const float* Xb = X + (size_t)b * NXX * DD;

    float acc[4][4] = {};

    const int lk = tid >> 4;       // 0..15 k row
    const int lq = (tid & 15) << 2;

    for (int kc = 0; kc < NXX; kc += 16) {
        *(float4*)&As[lk][lq] = *(const float4*)&Ab[(size_t)(kc + lk) * NRR + r0 + lq];
        *(float4*)&Xs[lk][lq] = *(const float4*)&Xb[(size_t)(kc + lk) * DD + e0 + lq];
        __syncthreads();
#pragma unroll
        for (int k = 0; k < 16; k++) {
            float4 a = *(const float4*)&As[k][ty << 2];
            float4 xv = *(const float4*)&Xs[k][tx << 2];
            float av[4] = {a.x, a.y, a.z, a.w};
            float ev[4] = {xv.x, xv.y, xv.z, xv.w};
#pragma unroll
            for (int i = 0; i < 4; i++)
#pragma unroll
                for (int j = 0; j < 4; j++)
                    acc[i][j] = fmaf(av[i], ev[j], acc[i][j]);
        }
        __syncthreads();
    }

#pragma unroll
    for (int i = 0; i < 4; i++) {
        float4 o = {acc[i][0], acc[i][1], acc[i][2], acc[i][3]};
        *(float4*)&out[((size_t)b * NRR + r0 + (ty << 2) + i) * DD + e0 + (tx << 2)] = o;
    }
}

// ---------------------------------------------------------------------------
extern "C" void kernel_launch(void* const* d_in, const int* in_sizes, int n_in,
                              void* d_out, int out_size)
{
    const float* X     = (const float*)d_in[0];
    const float* ref   = (const float*)d_in[1];
    const float* W_X   = (const float*)d_in[2];
    const float* b_X   = (const float*)d_in[3];
    const float* W_ref = (const float*)d_in[4];
    const float* b_ref = (const float*)d_in[5];
    const float* v_w   = (const float*)d_in[6];
    const float* v_b   = (const float*)d_in[7];
    float* out = (float*)d_out;

    float *hX, *hR, *S, *attn;
    cudaGetSymbolAddress((void**)&hX,   g_hX);
    cudaGetSymbolAddress((void**)&hR,   g_hR);
    cudaGetSymbolAddress((void**)&S,    g_S);
    cudaGetSymbolAddress((void**)&attn, g_attn);

    // Projections: [B*N, D] @ [H, D]^T + bias
    proj_kernel<<<dim3(BB * NXX / 64, HH / 64), 256>>>(X, W_X, b_X, hX);
    proj_kernel<<<dim3(BB * NRR / 64, HH / 64), 256>>>(ref, W_ref, b_ref, hR);

    // Scores (tanh, MUFU-bound)
    score_kernel<<<dim3(NXX / 32, NRR / 32, BB), 256>>>(hX, hR, v_w, v_b, S);

    // Softmax over x
    softmax_kernel<<<dim3(NRR / 32, BB), 256>>>(S, attn);

    // Weighted sum: attn^T @ X per batch
    outgemm_kernel<<<dim3(NRR / 64, DD / 64, BB), 256>>>(attn, X, out);
}

// round 2
// speedup vs baseline: 1.0196x; 1.0196x over previous
#include <cuda_runtime.h>
#include <cuda_fp16.h>

// Problem constants (fixed by the dataset)
#define BB 8
#define NXX 512
#define NRR 512
#define DD 256
#define HH 256

// Scratch (no cudaMalloc allowed)
__device__ float g_hX[BB * NXX * HH];       // [b, x, h]
__device__ float g_hR[BB * NRR * HH];       // [b, r, h]
__device__ float g_S[BB * NXX * NRR];       // [b, x, r]
__device__ float g_attn[BB * NXX * NRR];    // [b, x, r]

// ---------------------------------------------------------------------------
// Kernel 1: projection GEMM  out[n,h] = sum_d A[n,d] * W[h,d] + bias[h]
// gridDim.z selects (X,W_X,b_X)->hX  vs  (ref,W_ref,b_ref)->hR.
// 64x64 tile, 256 threads, 4x4 per thread.
// ---------------------------------------------------------------------------
__global__ __launch_bounds__(256) void proj_kernel(
    const float* __restrict__ A0, const float* __restrict__ W0,
    const float* __restrict__ bias0, float* __restrict__ out0,
    const float* __restrict__ A1, const float* __restrict__ W1,
    const float* __restrict__ bias1, float* __restrict__ out1)
{
    const float* A    = blockIdx.z ? A1 : A0;
    const float* W    = blockIdx.z ? W1 : W0;
    const float* bias = blockIdx.z ? bias1 : bias0;
    float* out        = blockIdx.z ? out1 : out0;

    __shared__ float As[16][64];
    __shared__ float Ws[16][64];
    const int tid = threadIdx.x;
    const int tx = tid & 15;        // n-dim
    const int ty = tid >> 4;        // m-dim
    const int m0 = blockIdx.x * 64;
    const int n0 = blockIdx.y * 64;

    float acc[4][4] = {};

    const int lr = tid >> 2;              // 0..63 row within tile
    const int lk = (tid & 3) << 2;        // 0,4,8,12 within k-chunk

    for (int kc = 0; kc < DD; kc += 16) {
        float4 va = *(const float4*)&A[(m0 + lr) * DD + kc + lk];
        float4 vw = *(const float4*)&W[(n0 + lr) * DD + kc + lk];
        As[lk + 0][lr] = va.x; As[lk + 1][lr] = va.y;
        As[lk + 2][lr] = va.z; As[lk + 3][lr] = va.w;
        Ws[lk + 0][lr] = vw.x; Ws[lk + 1][lr] = vw.y;
        Ws[lk + 2][lr] = vw.z; Ws[lk + 3][lr] = vw.w;
        __syncthreads();
#pragma unroll
        for (int k = 0; k < 16; k++) {
            float4 a = *(const float4*)&As[k][ty << 2];
            float4 w = *(const float4*)&Ws[k][tx << 2];
            float av[4] = {a.x, a.y, a.z, a.w};
            float wv[4] = {w.x, w.y, w.z, w.w};
#pragma unroll
            for (int i = 0; i < 4; i++)
#pragma unroll
                for (int j = 0; j < 4; j++)
                    acc[i][j] = fmaf(av[i], wv[j], acc[i][j]);
        }
        __syncthreads();
    }

    float4 bv = *(const float4*)&bias[n0 + (tx << 2)];
#pragma unroll
    for (int i = 0; i < 4; i++) {
        float4 o;
        o.x = acc[i][0] + bv.x; o.y = acc[i][1] + bv.y;
        o.z = acc[i][2] + bv.z; o.w = acc[i][3] + bv.w;
        *(float4*)&out[(m0 + (ty << 2) + i) * HH + n0 + (tx << 2)] = o;
    }
}

// ---------------------------------------------------------------------------
// Kernel 2: scores  S[b,x,r] = sum_h tanh(hX[b,x,h] + hR[b,r,h]) * v[h] + vb
// f16x2 path: h processed in pairs via tanh.approx.f16x2 (2 values / MUFU op).
// Accumulation stays fp32. Block = 32x x 32r tile; full H=256 tile in smem.
// ---------------------------------------------------------------------------
__global__ __launch_bounds__(256) void score_kernel(
    const float* __restrict__ hX, const float* __restrict__ hR,
    const float* __restrict__ vw, const float* __restrict__ vb,
    float* __restrict__ S)
{
    __shared__ __half2 hXs[32][128];   // [x][h-pair], broadcast reads per warp
    __shared__ __half2 hRt[128][33];   // [h-pair][r], pad 1: conflict-free
    __shared__ float2  v_s[128];       // v in fp32 pairs

    const int x0 = blockIdx.x * 32, r0 = blockIdx.y * 32, b = blockIdx.z;
    const int tid = threadIdx.x;
    const int lr = tid & 31;           // r lane
    const int w  = tid >> 5;           // warp -> x group of 4

    if (tid < 128)
        v_s[tid] = make_float2(vw[2 * tid], vw[2 * tid + 1]);

    const float* hXb = hX + (size_t)(b * NXX + x0) * HH;
    const float* hRb = hR + (size_t)(b * NRR + r0) * HH;

    // load + convert hX tile (row-major pairs): 32 rows x 64 float4
    for (int i = tid; i < 32 * 64; i += 256) {
        int row = i >> 6, q = i & 63;
        float4 vx = *(const float4*)&hXb[row * HH + (q << 2)];
        hXs[row][2 * q    ] = __floats2half2_rn(vx.x, vx.y);
        hXs[row][2 * q + 1] = __floats2half2_rn(vx.z, vx.w);
    }
    // load + convert hR tile transposed
    for (int i = tid; i < 32 * 64; i += 256) {
        int row = i >> 6, q = i & 63;
        float4 vr = *(const float4*)&hRb[row * HH + (q << 2)];
        hRt[2 * q    ][row] = __floats2half2_rn(vr.x, vr.y);
        hRt[2 * q + 1][row] = __floats2half2_rn(vr.z, vr.w);
    }
    __syncthreads();

    float acc[4] = {0.f, 0.f, 0.f, 0.f};

#pragma unroll 4
    for (int hp = 0; hp < 128; hp++) {
        __half2 hr2 = hRt[hp][lr];
        float2 v2 = v_s[hp];
#pragma unroll
        for (int j = 0; j < 4; j++) {
            __half2 t2 = __hadd2(hXs[(w << 2) + j][hp], hr2);
            unsigned u = *(unsigned*)&t2;
            asm("tanh.approx.f16x2 %0, %0;" : "+r"(u));
            __half2 th = *(__half2*)&u;
            acc[j] = fmaf(__low2float(th), v2.x,
                     fmaf(__high2float(th), v2.y, acc[j]));
        }
    }

    const float vbv = vb[0];
#pragma unroll
    for (int j = 0; j < 4; j++) {
        int x = x0 + (w << 2) + j;
        S[((size_t)b * NXX + x) * NRR + r0 + lr] = acc[j] + vbv;
    }
}

// ---------------------------------------------------------------------------
// Kernel 3: softmax over x (dim 1).  Block handles (b, 32 r's), coalesced.
// ---------------------------------------------------------------------------
__global__ __launch_bounds__(256) void softmax_kernel(
    const float* __restrict__ S, float* __restrict__ attn)
{
    const int r0 = blockIdx.x * 32;
    const int b  = blockIdx.y;
    const int tid = threadIdx.x;
    const int tr = tid & 31;       // r lane
    const int tg = tid >> 5;       // x group (8 groups of 64)

    __shared__ float red[8][32];

    const float* Sb = S + (size_t)b * NXX * NRR + r0;
    float* Ab = attn + (size_t)b * NXX * NRR + r0;

    float m = -1e30f;
    for (int x = tg * 64; x < tg * 64 + 64; x++)
        m = fmaxf(m, Sb[(size_t)x * NRR + tr]);
    red[tg][tr] = m;
    __syncthreads();
    if (tg == 0) {
        float mm = red[0][tr];
#pragma unroll
        for (int i = 1; i < 8; i++) mm = fmaxf(mm, red[i][tr]);
        red[0][tr] = mm;
    }
    __syncthreads();
    const float M = red[0][tr];
    __syncthreads();

    float s = 0.f;
    for (int x = tg * 64; x < tg * 64 + 64; x++)
        s += __expf(Sb[(size_t)x * NRR + tr] - M);
    red[tg][tr] = s;
    __syncthreads();
    if (tg == 0) {
        float ss = red[0][tr];
#pragma unroll
        for (int i = 1; i < 8; i++) ss += red[i][tr];
        red[0][tr] = ss;
    }
    __syncthreads();
    const float inv = 1.0f / red[0][tr];

    for (int x = tg * 64; x < tg * 64 + 64; x++)
        Ab[(size_t)x * NRR + tr] = __expf(Sb[(size_t)x * NRR + tr] - M) * inv;
}

// ---------------------------------------------------------------------------
// Kernel 4: out[b,r,e] = sum_x attn[b,x,r] * X[b,x,e]
// Both operands k(x)-major; 64x64 tile, 4x4 per thread.
// ---------------------------------------------------------------------------
__global__ __launch_bounds__(256) void outgemm_kernel(
    const float* __restrict__ attn, const float* __restrict__ X,
    float* __restrict__ out)
{
    __shared__ float As[16][64];   // attn[k][r]
    __shared__ float Xs[16][64];   // X[k][e]
    const int r0 = blockIdx.x * 64;
    const int e0 = blockIdx.y * 64;
    const int b  = blockIdx.z;
    const int tid = threadIdx.x;
    const int tx = tid & 15;       // e
    const int ty = tid >> 4;       // r

    const float* Ab = attn + (size_t)b * NXX * NRR;
    const float* Xb = X + (size_t)b * NXX * DD;

    float acc[4][4] = {};

    const int lk = tid >> 4;       // 0..15 k row
    const int lq = (tid & 15) << 2;

    for (int kc = 0; kc < NXX; kc += 16) {
        *(float4*)&As[lk][lq] = *(const float4*)&Ab[(size_t)(kc + lk) * NRR + r0 + lq];
        *(float4*)&Xs[lk][lq] = *(const float4*)&Xb[(size_t)(kc + lk) * DD + e0 + lq];
        __syncthreads();
#pragma unroll
        for (int k = 0; k < 16; k++) {
            float4 a = *(const float4*)&As[k][ty << 2];
            float4 xv = *(const float4*)&Xs[k][tx << 2];
            float av[4] = {a.x, a.y, a.z, a.w};
            float ev[4] = {xv.x, xv.y, xv.z, xv.w};
#pragma unroll
            for (int i = 0; i < 4; i++)
#pragma unroll
                for (int j = 0; j < 4; j++)
                    acc[i][j] = fmaf(av[i], ev[j], acc[i][j]);
        }
        __syncthreads();
    }

#pragma unroll
    for (int i = 0; i < 4; i++) {
        float4 o = {acc[i][0], acc[i][1], acc[i][2], acc[i][3]};
        *(float4*)&out[((size_t)b * NRR + r0 + (ty << 2) + i) * DD + e0 + (tx << 2)] = o;
    }
}

// ---------------------------------------------------------------------------
extern "C" void kernel_launch(void* const* d_in, const int* in_sizes, int n_in,
                              void* d_out, int out_size)
{
    const float* X     = (const float*)d_in[0];
    const float* ref   = (const float*)d_in[1];
    const float* W_X   = (const float*)d_in[2];
    const float* b_X   = (const float*)d_in[3];
    const float* W_ref = (const float*)d_in[4];
    const float* b_ref = (const float*)d_in[5];
    const float* v_w   = (const float*)d_in[6];
    const float* v_b   = (const float*)d_in[7];
    float* out = (float*)d_out;

    float *hX, *hR, *S, *attn;
    cudaGetSymbolAddress((void**)&hX,   g_hX);
    cudaGetSymbolAddress((void**)&hR,   g_hR);
    cudaGetSymbolAddress((void**)&S,    g_S);
    cudaGetSymbolAddress((void**)&attn, g_attn);

    // Projections (both in one launch, z selects input set)
    proj_kernel<<<dim3(BB * NXX / 64, HH / 64, 2), 256>>>(
        X, W_X, b_X, hX, ref, W_ref, b_ref, hR);

    // Scores (tanh.f16x2, MUFU-bound)
    score_kernel<<<dim3(NXX / 32, NRR / 32, BB), 256>>>(hX, hR, v_w, v_b, S);

    // Softmax over x
    softmax_kernel<<<dim3(NRR / 32, BB), 256>>>(S, attn);

    // Weighted sum: attn^T @ X per batch
    outgemm_kernel<<<dim3(NRR / 64, DD / 64, BB), 256>>>(attn, X, out);
}

// round 3
// speedup vs baseline: 1.0234x; 1.0037x over previous
#include <cuda_runtime.h>
#include <cuda_fp16.h>

// Problem constants (fixed by the dataset)
#define BB 8
#define NXX 512
#define NRR 512
#define DD 256
#define HH 256

// Scratch (no cudaMalloc allowed)
__device__ float g_hX[BB * NXX * HH];       // [b, x, h]
__device__ float g_hR[BB * NRR * HH];       // [b, r, h]
__device__ float g_S[BB * NXX * NRR];       // [b, x, r]
__device__ float g_attn[BB * NXX * NRR];    // [b, x, r]

// ---------------------------------------------------------------------------
// Kernel 1: projection GEMM  out[n,h] = sum_d A[n,d] * W[h,d] + bias[h]
// gridDim.z selects (X,W_X,b_X)->hX  vs  (ref,W_ref,b_ref)->hR.
// 64x64 tile, 256 threads, 4x4 per thread.
// ---------------------------------------------------------------------------
__global__ __launch_bounds__(256) void proj_kernel(
    const float* __restrict__ A0, const float* __restrict__ W0,
    const float* __restrict__ bias0, float* __restrict__ out0,
    const float* __restrict__ A1, const float* __restrict__ W1,
    const float* __restrict__ bias1, float* __restrict__ out1)
{
    const float* A    = blockIdx.z ? A1 : A0;
    const float* W    = blockIdx.z ? W1 : W0;
    const float* bias = blockIdx.z ? bias1 : bias0;
    float* out        = blockIdx.z ? out1 : out0;

    __shared__ float As[16][64];
    __shared__ float Ws[16][64];
    const int tid = threadIdx.x;
    const int tx = tid & 15;        // n-dim
    const int ty = tid >> 4;        // m-dim
    const int m0 = blockIdx.x * 64;
    const int n0 = blockIdx.y * 64;

    float acc[4][4] = {};

    const int lr = tid >> 2;              // 0..63 row within tile
    const int lk = (tid & 3) << 2;        // 0,4,8,12 within k-chunk

    for (int kc = 0; kc < DD; kc += 16) {
        float4 va = *(const float4*)&A[(m0 + lr) * DD + kc + lk];
        float4 vw = *(const float4*)&W[(n0 + lr) * DD + kc + lk];
        As[lk + 0][lr] = va.x; As[lk + 1][lr] = va.y;
        As[lk + 2][lr] = va.z; As[lk + 3][lr] = va.w;
        Ws[lk + 0][lr] = vw.x; Ws[lk + 1][lr] = vw.y;
        Ws[lk + 2][lr] = vw.z; Ws[lk + 3][lr] = vw.w;
        __syncthreads();
#pragma unroll
        for (int k = 0; k < 16; k++) {
            float4 a = *(const float4*)&As[k][ty << 2];
            float4 w = *(const float4*)&Ws[k][tx << 2];
            float av[4] = {a.x, a.y, a.z, a.w};
            float wv[4] = {w.x, w.y, w.z, w.w};
#pragma unroll
            for (int i = 0; i < 4; i++)
#pragma unroll
                for (int j = 0; j < 4; j++)
                    acc[i][j] = fmaf(av[i], wv[j], acc[i][j]);
        }
        __syncthreads();
    }

    float4 bv = *(const float4*)&bias[n0 + (tx << 2)];
#pragma unroll
    for (int i = 0; i < 4; i++) {
        float4 o;
        o.x = acc[i][0] + bv.x; o.y = acc[i][1] + bv.y;
        o.z = acc[i][2] + bv.z; o.w = acc[i][3] + bv.w;
        *(float4*)&out[(m0 + (ty << 2) + i) * HH + n0 + (tx << 2)] = o;
    }
}

// ---------------------------------------------------------------------------
// Kernel 2: scores  S[b,x,r] = sum_h tanh(hX[b,x,h] + hR[b,r,h]) * v[h] + vb
// tanh.approx.f16x2 (2 h / MUFU op). HFMA2 accumulation in half2 over chunks
// of 8 h-pairs (16 h); converted to fp32 once per chunk -> F2F amortized 8x.
// Block = 32x x 32r tile; full H=256 tile in smem.
// ---------------------------------------------------------------------------
__global__ __launch_bounds__(256) void score_kernel(
    const float* __restrict__ hX, const float* __restrict__ hR,
    const float* __restrict__ vw, const float* __restrict__ vb,
    float* __restrict__ S)
{
    __shared__ __half2 hXs[32][128];   // [x][h-pair], broadcast reads per warp
    __shared__ __half2 hRt[128][33];   // [h-pair][r], pad 1: conflict-free
    __shared__ __half2 v_h[128];       // v in half2 pairs

    const int x0 = blockIdx.x * 32, r0 = blockIdx.y * 32, b = blockIdx.z;
    const int tid = threadIdx.x;
    const int lr = tid & 31;           // r lane
    const int w  = tid >> 5;           // warp -> x group of 4

    if (tid < 128)
        v_h[tid] = __floats2half2_rn(vw[2 * tid], vw[2 * tid + 1]);

    const float* hXb = hX + (size_t)(b * NXX + x0) * HH;
    const float* hRb = hR + (size_t)(b * NRR + r0) * HH;

    // load + convert hX tile (row-major pairs): 32 rows x 64 float4
    for (int i = tid; i < 32 * 64; i += 256) {
        int row = i >> 6, q = i & 63;
        float4 vx = *(const float4*)&hXb[row * HH + (q << 2)];
        hXs[row][2 * q    ] = __floats2half2_rn(vx.x, vx.y);
        hXs[row][2 * q + 1] = __floats2half2_rn(vx.z, vx.w);
    }
    // load + convert hR tile transposed
    for (int i = tid; i < 32 * 64; i += 256) {
        int row = i >> 6, q = i & 63;
        float4 vr = *(const float4*)&hRb[row * HH + (q << 2)];
        hRt[2 * q    ][row] = __floats2half2_rn(vr.x, vr.y);
        hRt[2 * q + 1][row] = __floats2half2_rn(vr.z, vr.w);
    }
    __syncthreads();

    float acc[4] = {0.f, 0.f, 0.f, 0.f};

    for (int hc = 0; hc < 16; hc++) {          // 16 chunks of 8 h-pairs
        __half2 a2[4];
#pragma unroll
        for (int j = 0; j < 4; j++) a2[j] = __float2half2_rn(0.f);
#pragma unroll
        for (int k = 0; k < 8; k++) {
            const int hp = hc * 8 + k;
            __half2 hr2 = hRt[hp][lr];
            __half2 v2  = v_h[hp];
#pragma unroll
            for (int j = 0; j < 4; j++) {
                __half2 t2 = __hadd2(hXs[(w << 2) + j][hp], hr2);
                unsigned u = *(unsigned*)&t2;
                asm("tanh.approx.f16x2 %0, %0;" : "+r"(u));
                a2[j] = __hfma2(*(__half2*)&u, v2, a2[j]);
            }
        }
#pragma unroll
        for (int j = 0; j < 4; j++)
            acc[j] += __low2float(a2[j]) + __high2float(a2[j]);
    }

    const float vbv = vb[0];
#pragma unroll
    for (int j = 0; j < 4; j++) {
        int x = x0 + (w << 2) + j;
        S[((size_t)b * NXX + x) * NRR + r0 + lr] = acc[j] + vbv;
    }
}

// ---------------------------------------------------------------------------
// Kernel 3: softmax over x (dim 1).  Block handles (b, 32 r's), coalesced.
// Pass 2 writes exp values to attn; pass 3 scales in place.
// ---------------------------------------------------------------------------
__global__ __launch_bounds__(256) void softmax_kernel(
    const float* __restrict__ S, float* __restrict__ attn)
{
    const int r0 = blockIdx.x * 32;
    const int b  = blockIdx.y;
    const int tid = threadIdx.x;
    const int tr = tid & 31;       // r lane
    const int tg = tid >> 5;       // x group (8 groups of 64)

    __shared__ float red[8][32];

    const float* Sb = S + (size_t)b * NXX * NRR + r0;
    float* Ab = attn + (size_t)b * NXX * NRR + r0;

    float m = -1e30f;
    for (int x = tg * 64; x < tg * 64 + 64; x++)
        m = fmaxf(m, Sb[(size_t)x * NRR + tr]);
    red[tg][tr] = m;
    __syncthreads();
    if (tg == 0) {
        float mm = red[0][tr];
#pragma unroll
        for (int i = 1; i < 8; i++) mm = fmaxf(mm, red[i][tr]);
        red[0][tr] = mm;
    }
    __syncthreads();
    const float M = red[0][tr];
    __syncthreads();

    float s = 0.f;
    for (int x = tg * 64; x < tg * 64 + 64; x++) {
        float e = __expf(Sb[(size_t)x * NRR + tr] - M);
        Ab[(size_t)x * NRR + tr] = e;
        s += e;
    }
    red[tg][tr] = s;
    __syncthreads();
    if (tg == 0) {
        float ss = red[0][tr];
#pragma unroll
        for (int i = 1; i < 8; i++) ss += red[i][tr];
        red[0][tr] = ss;
    }
    __syncthreads();
    const float inv = 1.0f / red[0][tr];

    for (int x = tg * 64; x < tg * 64 + 64; x++)
        Ab[(size_t)x * NRR + tr] *= inv;
}

// ---------------------------------------------------------------------------
// Kernel 4: out[b,r,e] = sum_x attn[b,x,r] * X[b,x,e]
// Both operands k(x)-major; 64x64 tile, k-chunk 64 (16 barriers total).
// ---------------------------------------------------------------------------
__global__ __launch_bounds__(256) void outgemm_kernel(
    const float* __restrict__ attn, const float* __restrict__ X,
    float* __restrict__ out)
{
    __shared__ float As[64][64];   // attn[k][r]
    __shared__ float Xs[64][64];   // X[k][e]
    const int r0 = blockIdx.x * 64;
    const int e0 = blockIdx.y * 64;
    const int b  = blockIdx.z;
    const int tid = threadIdx.x;
    const int tx = tid & 15;       // e
    const int ty = tid >> 4;       // r

    const float* Ab = attn + (size_t)b * NXX * NRR;
    const float* Xb = X + (size_t)b * NXX * DD;

    float acc[4][4] = {};

    for (int kc = 0; kc < NXX; kc += 64) {
        // 64x64 tile per matrix = 1024 float4; 256 threads -> 4 each, coalesced
        for (int i = tid; i < 64 * 16; i += 256) {
            int row = i >> 4, q = (i & 15) << 2;
            *(float4*)&As[row][q] = *(const float4*)&Ab[(size_t)(kc + row) * NRR + r0 + q];
            *(float4*)&Xs[row][q] = *(const float4*)&Xb[(size_t)(kc + row) * DD + e0 + q];
        }
        __syncthreads();
#pragma unroll 8
        for (int k = 0; k < 64; k++) {
            float4 a = *(const float4*)&As[k][ty << 2];
            float4 xv = *(const float4*)&Xs[k][tx << 2];
            float av[4] = {a.x, a.y, a.z, a.w};
            float ev[4] = {xv.x, xv.y, xv.z, xv.w};
#pragma unroll
            for (int i = 0; i < 4; i++)
#pragma unroll
                for (int j = 0; j < 4; j++)
                    acc[i][j] = fmaf(av[i], ev[j], acc[i][j]);
        }
        __syncthreads();
    }

#pragma unroll
    for (int i = 0; i < 4; i++) {
        float4 o = {acc[i][0], acc[i][1], acc[i][2], acc[i][3]};
        *(float4*)&out[((size_t)b * NRR + r0 + (ty << 2) + i) * DD + e0 + (tx << 2)] = o;
    }
}

// ---------------------------------------------------------------------------
extern "C" void kernel_launch(void* const* d_in, const int* in_sizes, int n_in,
                              void* d_out, int out_size)
{
    const float* X     = (const float*)d_in[0];
    const float* ref   = (const float*)d_in[1];
    const float* W_X   = (const float*)d_in[2];
    const float* b_X   = (const float*)d_in[3];
    const float* W_ref = (const float*)d_in[4];
    const float* b_ref = (const float*)d_in[5];
    const float* v_w   = (const float*)d_in[6];
    const float* v_b   = (const float*)d_in[7];
    float* out = (float*)d_out;

    float *hX, *hR, *S, *attn;
    cudaGetSymbolAddress((void**)&hX,   g_hX);
    cudaGetSymbolAddress((void**)&hR,   g_hR);
    cudaGetSymbolAddress((void**)&S,    g_S);
    cudaGetSymbolAddress((void**)&attn, g_attn);

    // Projections (both in one launch, z selects input set)
    proj_kernel<<<dim3(BB * NXX / 64, HH / 64, 2), 256>>>(
        X, W_X, b_X, hX, ref, W_ref, b_ref, hR);

    // Scores (tanh.f16x2 + HFMA2 chunked accumulation, XU-bound)
    score_kernel<<<dim3(NXX / 32, NRR / 32, BB), 256>>>(hX, hR, v_w, v_b, S);

    // Softmax over x
    softmax_kernel<<<dim3(NRR / 32, BB), 256>>>(S, attn);

    // Weighted sum: attn^T @ X per batch
    outgemm_kernel<<<dim3(NRR / 64, DD / 64, BB), 256>>>(attn, X, out);
}

// round 4
// speedup vs baseline: 1.2116x; 1.1839x over previous
#include <cuda_runtime.h>
#include <cuda_fp16.h>

// Problem constants (fixed by the dataset)
#define BB 8
#define NXX 512
#define NRR 512
#define DD 256
#define HH 256

// Scratch (no cudaMalloc allowed)
__device__ float g_hX[BB * NXX * HH];       // [b, x, h]
__device__ float g_hR[BB * NRR * HH];       // [b, r, h]
__device__ float g_S[BB * NXX * NRR];       // [b, x, r]
__device__ float g_attn[BB * NXX * NRR];    // [b, x, r]

// ---------------------------------------------------------------------------
// tf32 MMA helpers (m16n8k8)
// ---------------------------------------------------------------------------
__device__ __forceinline__ unsigned f2tf32(float x) {
    unsigned r;
    asm("cvt.rna.tf32.f32 %0, %1;" : "=r"(r) : "f"(x));
    return r;
}

__device__ __forceinline__ void mma_tf32(float* c, const unsigned* a, const unsigned* b) {
    asm volatile(
        "mma.sync.aligned.m16n8k8.row.col.f32.tf32.tf32.f32 "
        "{%0,%1,%2,%3}, {%4,%5,%6,%7}, {%8,%9}, {%0,%1,%2,%3};\n"
        : "+f"(c[0]), "+f"(c[1]), "+f"(c[2]), "+f"(c[3])
        : "r"(a[0]), "r"(a[1]), "r"(a[2]), "r"(a[3]), "r"(b[0]), "r"(b[1]));
}

// ---------------------------------------------------------------------------
// Kernel 1: projection GEMM (tf32 tensor cores)
// out[m,h] = sum_d A[m,d] * W[h,d] + bias[h];  z selects (X)->hX vs (ref)->hR
// Block: 256 thr (8 warps), tile 128m x 64n, k-chunk 32. Warp tile 32x32.
// ---------------------------------------------------------------------------
__global__ __launch_bounds__(256) void proj_mma_kernel(
    const float* __restrict__ A0, const float* __restrict__ W0,
    const float* __restrict__ bias0, float* __restrict__ out0,
    const float* __restrict__ A1, const float* __restrict__ W1,
    const float* __restrict__ bias1, float* __restrict__ out1)
{
    const float* A    = blockIdx.z ? A1 : A0;
    const float* W    = blockIdx.z ? W1 : W0;
    const float* bias = blockIdx.z ? bias1 : bias0;
    float* out        = blockIdx.z ? out1 : out0;

    __shared__ unsigned As[128][36];   // [m][k], pad->stride 36: conflict-free frags
    __shared__ unsigned Ws[64][36];    // [n][k]

    const int tid  = threadIdx.x;
    const int lane = tid & 31;
    const int warp = tid >> 5;
    const int wm = warp >> 1;          // 0..3  -> m offset 32*wm
    const int wn = warp & 1;           // 0..1  -> n offset 32*wn
    const int m0 = blockIdx.x * 128;
    const int n0 = blockIdx.y * 64;

    const int fr = lane >> 2;          // fragment row group 0..7
    const int fc = lane & 3;           // fragment col group 0..3

    float c[2][4][4] = {};             // [m-tile 16][n-tile 8][regs]

    for (int kc = 0; kc < DD; kc += 32) {
        // Load A tile 128x32 (1024 float4), 8 threads per row -> coalesced
        for (int i = tid; i < 1024; i += 256) {
            int row = i >> 3, q = (i & 7) << 2;
            float4 v = *(const float4*)&A[(size_t)(m0 + row) * DD + kc + q];
            As[row][q + 0] = f2tf32(v.x); As[row][q + 1] = f2tf32(v.y);
            As[row][q + 2] = f2tf32(v.z); As[row][q + 3] = f2tf32(v.w);
        }
        // Load W tile 64x32 (512 float4)
        for (int i = tid; i < 512; i += 256) {
            int row = i >> 3, q = (i & 7) << 2;
            float4 v = *(const float4*)&W[(size_t)(n0 + row) * DD + kc + q];
            Ws[row][q + 0] = f2tf32(v.x); Ws[row][q + 1] = f2tf32(v.y);
            Ws[row][q + 2] = f2tf32(v.z); Ws[row][q + 3] = f2tf32(v.w);
        }
        __syncthreads();

#pragma unroll
        for (int ks = 0; ks < 4; ks++) {
            const int k = ks << 3;
            unsigned a[2][4], b[4][2];
#pragma unroll
            for (int mt = 0; mt < 2; mt++) {
                int mb = wm * 32 + mt * 16;
                a[mt][0] = As[mb + fr    ][k + fc    ];
                a[mt][1] = As[mb + fr + 8][k + fc    ];
                a[mt][2] = As[mb + fr    ][k + fc + 4];
                a[mt][3] = As[mb + fr + 8][k + fc + 4];
            }
#pragma unroll
            for (int nt = 0; nt < 4; nt++) {
                int nb = wn * 32 + nt * 8;
                b[nt][0] = Ws[nb + fr][k + fc    ];
                b[nt][1] = Ws[nb + fr][k + fc + 4];
            }
#pragma unroll
            for (int mt = 0; mt < 2; mt++)
#pragma unroll
                for (int nt = 0; nt < 4; nt++)
                    mma_tf32(c[mt][nt], a[mt], b[nt]);
        }
        __syncthreads();
    }

    // Epilogue: + bias, store
#pragma unroll
    for (int mt = 0; mt < 2; mt++) {
        int row0 = m0 + wm * 32 + mt * 16 + fr;
#pragma unroll
        for (int nt = 0; nt < 4; nt++) {
            int col = n0 + wn * 32 + nt * 8 + 2 * fc;
            float2 bv = *(const float2*)&bias[col];
            float2 o0 = {c[mt][nt][0] + bv.x, c[mt][nt][1] + bv.y};
            float2 o1 = {c[mt][nt][2] + bv.x, c[mt][nt][3] + bv.y};
            *(float2*)&out[(size_t)row0 * HH + col]       = o0;
            *(float2*)&out[(size_t)(row0 + 8) * HH + col] = o1;
        }
    }
}

// ---------------------------------------------------------------------------
// Kernel 2: scores  S[b,x,r] = sum_h tanh(hX[b,x,h] + hR[b,r,h]) * v[h] + vb
// f32 tanh path (MUFU lane-throughput bound; f16x2 gains nothing, costs error)
// ---------------------------------------------------------------------------
__global__ __launch_bounds__(256) void score_kernel(
    const float* __restrict__ hX, const float* __restrict__ hR,
    const float* __restrict__ vw, const float* __restrict__ vb,
    float* __restrict__ S)
{
    __shared__ float hXs[32][128];     // row-major: broadcast reads per warp
    __shared__ float hRt[128][33];     // transposed + pad: conflict-free by lane
    __shared__ float v_s[HH];

    const int x0 = blockIdx.x * 32, r0 = blockIdx.y * 32, b = blockIdx.z;
    const int tid = threadIdx.x;
    const int lr = tid & 31;           // r lane
    const int w  = tid >> 5;           // warp -> x group

    v_s[tid] = vw[tid];

    const float* hXb = hX + (size_t)(b * NXX + x0) * HH;
    const float* hRb = hR + (size_t)(b * NRR + r0) * HH;

    float acc[4] = {0.f, 0.f, 0.f, 0.f};

    for (int hc = 0; hc < 2; hc++) {
        __syncthreads();
        for (int i = tid; i < 32 * 32; i += 256) {
            int row = i >> 5, c4 = (i & 31) << 2;
            *(float4*)&hXs[row][c4] =
                *(const float4*)&hXb[row * HH + hc * 128 + c4];
        }
        for (int i = tid; i < 32 * 32; i += 256) {
            int row = i >> 5, c4 = (i & 31) << 2;
            float4 v = *(const float4*)&hRb[row * HH + hc * 128 + c4];
            hRt[c4 + 0][row] = v.x; hRt[c4 + 1][row] = v.y;
            hRt[c4 + 2][row] = v.z; hRt[c4 + 3][row] = v.w;
        }
        __syncthreads();

        const float* vv = &v_s[hc * 128];
#pragma unroll 4
        for (int h = 0; h < 128; h++) {
            float hr = hRt[h][lr];
            float vh = vv[h];
#pragma unroll
            for (int j = 0; j < 4; j++) {
                float t = hXs[(w << 2) + j][h] + hr;
                float th;
                asm("tanh.approx.f32 %0, %1;" : "=f"(th) : "f"(t));
                acc[j] = fmaf(th, vh, acc[j]);
            }
        }
    }

    const float vbv = vb[0];
#pragma unroll
    for (int j = 0; j < 4; j++) {
        int x = x0 + (w << 2) + j;
        S[((size_t)b * NXX + x) * NRR + r0 + lr] = acc[j] + vbv;
    }
}

// ---------------------------------------------------------------------------
// Kernel 3: softmax over x (dim 1).  Block handles (b, 32 r's), coalesced.
// ---------------------------------------------------------------------------
__global__ __launch_bounds__(256) void softmax_kernel(
    const float* __restrict__ S, float* __restrict__ attn)
{
    const int r0 = blockIdx.x * 32;
    const int b  = blockIdx.y;
    const int tid = threadIdx.x;
    const int tr = tid & 31;       // r lane
    const int tg = tid >> 5;       // x group (8 groups of 64)

    __shared__ float red[8][32];

    const float* Sb = S + (size_t)b * NXX * NRR + r0;
    float* Ab = attn + (size_t)b * NXX * NRR + r0;

    float m = -1e30f;
    for (int x = tg * 64; x < tg * 64 + 64; x++)
        m = fmaxf(m, Sb[(size_t)x * NRR + tr]);
    red[tg][tr] = m;
    __syncthreads();
    if (tg == 0) {
        float mm = red[0][tr];
#pragma unroll
        for (int i = 1; i < 8; i++) mm = fmaxf(mm, red[i][tr]);
        red[0][tr] = mm;
    }
    __syncthreads();
    const float M = red[0][tr];
    __syncthreads();

    float s = 0.f;
    for (int x = tg * 64; x < tg * 64 + 64; x++) {
        float e = __expf(Sb[(size_t)x * NRR + tr] - M);
        Ab[(size_t)x * NRR + tr] = e;
        s += e;
    }
    red[tg][tr] = s;
    __syncthreads();
    if (tg == 0) {
        float ss = red[0][tr];
#pragma unroll
        for (int i = 1; i < 8; i++) ss += red[i][tr];
        red[0][tr] = ss;
    }
    __syncthreads();
    const float inv = 1.0f / red[0][tr];

    for (int x = tg * 64; x < tg * 64 + 64; x++)
        Ab[(size_t)x * NRR + tr] *= inv;
}

// ---------------------------------------------------------------------------
// Kernel 4: out[b,r,e] = sum_x attn[b,x,r] * X[b,x,e]   (tf32 tensor cores)
// attn is [k=x][m=r], X is [k=x][n=e]. Block tile 128r x 64e, k-chunk 32.
// ---------------------------------------------------------------------------
__global__ __launch_bounds__(256) void outgemm_mma_kernel(
    const float* __restrict__ attn, const float* __restrict__ X,
    float* __restrict__ out)
{
    __shared__ unsigned As[32][136];   // [k][r], stride 136: conflict-free frags
    __shared__ unsigned Xs[32][72];    // [k][e], stride 72

    const int tid  = threadIdx.x;
    const int lane = tid & 31;
    const int warp = tid >> 5;
    const int wm = warp >> 1;          // 0..3
    const int wn = warp & 1;           // 0..1
    const int r0 = blockIdx.x * 128;
    const int e0 = blockIdx.y * 64;
    const int b  = blockIdx.z;

    const int fr = lane >> 2;
    const int fc = lane & 3;

    const float* Ab = attn + (size_t)b * NXX * NRR;
    const float* Xb = X + (size_t)b * NXX * DD;

    float c[2][4][4] = {};

    for (int kc = 0; kc < NXX; kc += 32) {
        // attn tile 32x128 (1024 float4), 32 float4 per row -> coalesced
        for (int i = tid; i < 1024; i += 256) {
            int row = i >> 5, q = (i & 31) << 2;
            float4 v = *(const float4*)&Ab[(size_t)(kc + row) * NRR + r0 + q];
            As[row][q + 0] = f2tf32(v.x); As[row][q + 1] = f2tf32(v.y);
            As[row][q + 2] = f2tf32(v.z); As[row][q + 3] = f2tf32(v.w);
        }
        // X tile 32x64 (512 float4)
        for (int i = tid; i < 512; i += 256) {
            int row = i >> 4, q = (i & 15) << 2;
            float4 v = *(const float4*)&Xb[(size_t)(kc + row) * DD + e0 + q];
            Xs[row][q + 0] = f2tf32(v.x); Xs[row][q + 1] = f2tf32(v.y);
            Xs[row][q + 2] = f2tf32(v.z); Xs[row][q + 3] = f2tf32(v.w);
        }
        __syncthreads();

#pragma unroll
        for (int ks = 0; ks < 4; ks++) {
            const int k = ks << 3;
            unsigned a[2][4], bfr[4][2];
#pragma unroll
            for (int mt = 0; mt < 2; mt++) {
                int mb = wm * 32 + mt * 16;
                a[mt][0] = As[k + fc    ][mb + fr    ];
                a[mt][1] = As[k + fc    ][mb + fr + 8];
                a[mt][2] = As[k + fc + 4][mb + fr    ];
                a[mt][3] = As[k + fc + 4][mb + fr + 8];
            }
#pragma unroll
            for (int nt = 0; nt < 4; nt++) {
                int nb = wn * 32 + nt * 8;
                bfr[nt][0] = Xs[k + fc    ][nb + fr];
                bfr[nt][1] = Xs[k + fc + 4][nb + fr];
            }
#pragma unroll
            for (int mt = 0; mt < 2; mt++)
#pragma unroll
                for (int nt = 0; nt < 4; nt++)
                    mma_tf32(c[mt][nt], a[mt], bfr[nt]);
        }
        __syncthreads();
    }

#pragma unroll
    for (int mt = 0; mt < 2; mt++) {
        int row0 = r0 + wm * 32 + mt * 16 + fr;
#pragma unroll
        for (int nt = 0; nt < 4; nt++) {
            int col = e0 + wn * 32 + nt * 8 + 2 * fc;
            float2 o0 = {c[mt][nt][0], c[mt][nt][1]};
            float2 o1 = {c[mt][nt][2], c[mt][nt][3]};
            *(float2*)&out[((size_t)b * NRR + row0) * DD + col]     = o0;
            *(float2*)&out[((size_t)b * NRR + row0 + 8) * DD + col] = o1;
        }
    }
}

// ---------------------------------------------------------------------------
extern "C" void kernel_launch(void* const* d_in, const int* in_sizes, int n_in,
                              void* d_out, int out_size)
{
    const float* X     = (const float*)d_in[0];
    const float* ref   = (const float*)d_in[1];
    const float* W_X   = (const float*)d_in[2];
    const float* b_X   = (const float*)d_in[3];
    const float* W_ref = (const float*)d_in[4];
    const float* b_ref = (const float*)d_in[5];
    const float* v_w   = (const float*)d_in[6];
    const float* v_b   = (const float*)d_in[7];
    float* out = (float*)d_out;

    float *hX, *hR, *S, *attn;
    cudaGetSymbolAddress((void**)&hX,   g_hX);
    cudaGetSymbolAddress((void**)&hR,   g_hR);
    cudaGetSymbolAddress((void**)&S,    g_S);
    cudaGetSymbolAddress((void**)&attn, g_attn);

    // Projections (tf32 MMA; z selects input set)
    proj_mma_kernel<<<dim3(BB * NXX / 128, HH / 64, 2), 256>>>(
        X, W_X, b_X, hX, ref, W_ref, b_ref, hR);

    // Scores (f32 tanh, MUFU lane-throughput bound)
    score_kernel<<<dim3(NXX / 32, NRR / 32, BB), 256>>>(hX, hR, v_w, v_b, S);

    // Softmax over x
    softmax_kernel<<<dim3(NRR / 32, BB), 256>>>(S, attn);

    // Weighted sum: attn^T @ X per batch (tf32 MMA)
    outgemm_mma_kernel<<<dim3(NRR / 128, DD / 64, BB), 256>>>(attn, X, out);
}

// round 6
// speedup vs baseline: 1.2760x; 1.0531x over previous
#include <cuda_runtime.h>
#include <cuda_fp16.h>

// Problem constants (fixed by the dataset)
#define BB 8
#define NXX 512
#define NRR 512
#define DD 256
#define HH 256

// Scratch (no cudaMalloc allowed)
__device__ float g_hX[BB * NXX * HH];       // [b, x, h]
__device__ float g_hR[BB * NRR * HH];       // [b, r, h]
__device__ float g_S[BB * NXX * NRR];       // [b, x, r]
__device__ float g_attn[BB * NXX * NRR];    // [b, x, r]

// ---------------------------------------------------------------------------
// tf32 MMA helpers (m16n8k8)
// ---------------------------------------------------------------------------
__device__ __forceinline__ unsigned f2tf32(float x) {
    unsigned r;
    asm("cvt.rna.tf32.f32 %0, %1;" : "=r"(r) : "f"(x));
    return r;
}

__device__ __forceinline__ void mma_tf32(float* c, const unsigned* a, const unsigned* b) {
    asm volatile(
        "mma.sync.aligned.m16n8k8.row.col.f32.tf32.tf32.f32 "
        "{%0,%1,%2,%3}, {%4,%5,%6,%7}, {%8,%9}, {%0,%1,%2,%3};\n"
        : "+f"(c[0]), "+f"(c[1]), "+f"(c[2]), "+f"(c[3])
        : "r"(a[0]), "r"(a[1]), "r"(a[2]), "r"(a[3]), "r"(b[0]), "r"(b[1]));
}

// ---------------------------------------------------------------------------
// Kernel 1: projection GEMM (tf32 MMA, double-buffered)
// out[m,h] = sum_d A[m,d] * W[h,d] + bias[h];  z selects (X)->hX vs (ref)->hR
// Tile 128m x 64n, k-chunk 32, register-prefetch + 2 smem buffers.
// ---------------------------------------------------------------------------
__global__ __launch_bounds__(256) void proj_mma_kernel(
    const float* __restrict__ A0, const float* __restrict__ W0,
    const float* __restrict__ bias0, float* __restrict__ out0,
    const float* __restrict__ A1, const float* __restrict__ W1,
    const float* __restrict__ bias1, float* __restrict__ out1)
{
    const float* A    = blockIdx.z ? A1 : A0;
    const float* W    = blockIdx.z ? W1 : W0;
    const float* bias = blockIdx.z ? bias1 : bias0;
    float* out        = blockIdx.z ? out1 : out0;

    __shared__ unsigned As[2][128][36];   // [buf][m][k]
    __shared__ unsigned Ws[2][64][36];    // [buf][n][k]

    const int tid  = threadIdx.x;
    const int lane = tid & 31;
    const int warp = tid >> 5;
    const int wm = warp >> 1;          // 0..3
    const int wn = warp & 1;           // 0..1
    const int m0 = blockIdx.x * 128;
    const int n0 = blockIdx.y * 64;

    const int fr = lane >> 2;
    const int fc = lane & 3;

    // per-thread load slots: A 4 float4, W 2 float4
    const int ar = tid >> 1;                 // 0..127 (A row); 2 thr/row
    const int aq = (tid & 1) << 4;           // 0 or 16 (col offset, 4 float4)
    const int wr = tid >> 2;                 // 0..63 (W row); 4 thr/row
    const int wq = (tid & 3) << 3;           // 0,8,16,24 (2 float4)

    float c[2][4][4] = {};

    // preload k-chunk 0 into buffer 0
    {
        const float* Arow = &A[(size_t)(m0 + ar) * DD + aq];
        const float* Wrow = &W[(size_t)(n0 + wr) * DD + wq];
#pragma unroll
        for (int u = 0; u < 4; u++) {
            float4 v = *(const float4*)&Arow[4 * u];
            As[0][ar][aq + 4*u + 0] = f2tf32(v.x); As[0][ar][aq + 4*u + 1] = f2tf32(v.y);
            As[0][ar][aq + 4*u + 2] = f2tf32(v.z); As[0][ar][aq + 4*u + 3] = f2tf32(v.w);
        }
#pragma unroll
        for (int u = 0; u < 2; u++) {
            float4 v = *(const float4*)&Wrow[4 * u];
            Ws[0][wr][wq + 4*u + 0] = f2tf32(v.x); Ws[0][wr][wq + 4*u + 1] = f2tf32(v.y);
            Ws[0][wr][wq + 4*u + 2] = f2tf32(v.z); Ws[0][wr][wq + 4*u + 3] = f2tf32(v.w);
        }
    }
    __syncthreads();

    int cur = 0;
    for (int kc = 0; kc < DD; kc += 32) {
        const int nk = kc + 32;
        float4 pa[4], pw[2];
        if (nk < DD) {
            const float* Arow = &A[(size_t)(m0 + ar) * DD + nk + aq];
            const float* Wrow = &W[(size_t)(n0 + wr) * DD + nk + wq];
#pragma unroll
            for (int u = 0; u < 4; u++) pa[u] = *(const float4*)&Arow[4 * u];
#pragma unroll
            for (int u = 0; u < 2; u++) pw[u] = *(const float4*)&Wrow[4 * u];
        }

#pragma unroll
        for (int ks = 0; ks < 4; ks++) {
            const int k = ks << 3;
            unsigned a[2][4], b[4][2];
#pragma unroll
            for (int mt = 0; mt < 2; mt++) {
                int mb = wm * 32 + mt * 16;
                a[mt][0] = As[cur][mb + fr    ][k + fc    ];
                a[mt][1] = As[cur][mb + fr + 8][k + fc    ];
                a[mt][2] = As[cur][mb + fr    ][k + fc + 4];
                a[mt][3] = As[cur][mb + fr + 8][k + fc + 4];
            }
#pragma unroll
            for (int nt = 0; nt < 4; nt++) {
                int nb = wn * 32 + nt * 8;
                b[nt][0] = Ws[cur][nb + fr][k + fc    ];
                b[nt][1] = Ws[cur][nb + fr][k + fc + 4];
            }
#pragma unroll
            for (int mt = 0; mt < 2; mt++)
#pragma unroll
                for (int nt = 0; nt < 4; nt++)
                    mma_tf32(c[mt][nt], a[mt], b[nt]);
        }

        if (nk < DD) {
            const int nxt = cur ^ 1;
#pragma unroll
            for (int u = 0; u < 4; u++) {
                As[nxt][ar][aq + 4*u + 0] = f2tf32(pa[u].x);
                As[nxt][ar][aq + 4*u + 1] = f2tf32(pa[u].y);
                As[nxt][ar][aq + 4*u + 2] = f2tf32(pa[u].z);
                As[nxt][ar][aq + 4*u + 3] = f2tf32(pa[u].w);
            }
#pragma unroll
            for (int u = 0; u < 2; u++) {
                Ws[nxt][wr][wq + 4*u + 0] = f2tf32(pw[u].x);
                Ws[nxt][wr][wq + 4*u + 1] = f2tf32(pw[u].y);
                Ws[nxt][wr][wq + 4*u + 2] = f2tf32(pw[u].z);
                Ws[nxt][wr][wq + 4*u + 3] = f2tf32(pw[u].w);
            }
            __syncthreads();
            cur = nxt;
        }
    }

#pragma unroll
    for (int mt = 0; mt < 2; mt++) {
        int row0 = m0 + wm * 32 + mt * 16 + fr;
#pragma unroll
        for (int nt = 0; nt < 4; nt++) {
            int col = n0 + wn * 32 + nt * 8 + 2 * fc;
            float2 bv = *(const float2*)&bias[col];
            float2 o0 = {c[mt][nt][0] + bv.x, c[mt][nt][1] + bv.y};
            float2 o1 = {c[mt][nt][2] + bv.x, c[mt][nt][3] + bv.y};
            *(float2*)&out[(size_t)row0 * HH + col]       = o0;
            *(float2*)&out[(size_t)(row0 + 8) * HH + col] = o1;
        }
    }
}

// ---------------------------------------------------------------------------
// Kernel 2: scores  S[b,x,r] = sum_h tanh(hX[b,x,h] + hR[b,r,h]) * v[h] + vb
// f32 tanh path (MUFU lane-throughput bound — this is the hard floor)
// ---------------------------------------------------------------------------
__global__ __launch_bounds__(256) void score_kernel(
    const float* __restrict__ hX, const float* __restrict__ hR,
    const float* __restrict__ vw, const float* __restrict__ vb,
    float* __restrict__ S)
{
    __shared__ float hXs[32][128];
    __shared__ float hRt[128][33];
    __shared__ float v_s[HH];

    const int x0 = blockIdx.x * 32, r0 = blockIdx.y * 32, b = blockIdx.z;
    const int tid = threadIdx.x;
    const int lr = tid & 31;
    const int w  = tid >> 5;

    v_s[tid] = vw[tid];

    const float* hXb = hX + (size_t)(b * NXX + x0) * HH;
    const float* hRb = hR + (size_t)(b * NRR + r0) * HH;

    float acc[4] = {0.f, 0.f, 0.f, 0.f};

    for (int hc = 0; hc < 2; hc++) {
        __syncthreads();
        for (int i = tid; i < 32 * 32; i += 256) {
            int row = i >> 5, c4 = (i & 31) << 2;
            *(float4*)&hXs[row][c4] =
                *(const float4*)&hXb[row * HH + hc * 128 + c4];
        }
        for (int i = tid; i < 32 * 32; i += 256) {
            int row = i >> 5, c4 = (i & 31) << 2;
            float4 v = *(const float4*)&hRb[row * HH + hc * 128 + c4];
            hRt[c4 + 0][row] = v.x; hRt[c4 + 1][row] = v.y;
            hRt[c4 + 2][row] = v.z; hRt[c4 + 3][row] = v.w;
        }
        __syncthreads();

        const float* vv = &v_s[hc * 128];
#pragma unroll 4
        for (int h = 0; h < 128; h++) {
            float hr = hRt[h][lr];
            float vh = vv[h];
#pragma unroll
            for (int j = 0; j < 4; j++) {
                float t = hXs[(w << 2) + j][h] + hr;
                float th;
                asm("tanh.approx.f32 %0, %1;" : "=f"(th) : "f"(t));
                acc[j] = fmaf(th, vh, acc[j]);
            }
        }
    }

    const float vbv = vb[0];
#pragma unroll
    for (int j = 0; j < 4; j++) {
        int x = x0 + (w << 2) + j;
        S[((size_t)b * NXX + x) * NRR + r0 + lr] = acc[j] + vbv;
    }
}

// ---------------------------------------------------------------------------
// Kernel 3: softmax over x (dim 1).  Block handles (b, 32 r's), coalesced.
// ---------------------------------------------------------------------------
__global__ __launch_bounds__(256) void softmax_kernel(
    const float* __restrict__ S, float* __restrict__ attn)
{
    const int r0 = blockIdx.x * 32;
    const int b  = blockIdx.y;
    const int tid = threadIdx.x;
    const int tr = tid & 31;
    const int tg = tid >> 5;

    __shared__ float red[8][32];

    const float* Sb = S + (size_t)b * NXX * NRR + r0;
    float* Ab = attn + (size_t)b * NXX * NRR + r0;

    float m = -1e30f;
    for (int x = tg * 64; x < tg * 64 + 64; x++)
        m = fmaxf(m, Sb[(size_t)x * NRR + tr]);
    red[tg][tr] = m;
    __syncthreads();
    if (tg == 0) {
        float mm = red[0][tr];
#pragma unroll
        for (int i = 1; i < 8; i++) mm = fmaxf(mm, red[i][tr]);
        red[0][tr] = mm;
    }
    __syncthreads();
    const float M = red[0][tr];
    __syncthreads();

    float s = 0.f;
    for (int x = tg * 64; x < tg * 64 + 64; x++) {
        float e = __expf(Sb[(size_t)x * NRR + tr] - M);
        Ab[(size_t)x * NRR + tr] = e;
        s += e;
    }
    red[tg][tr] = s;
    __syncthreads();
    if (tg == 0) {
        float ss = red[0][tr];
#pragma unroll
        for (int i = 1; i < 8; i++) ss += red[i][tr];
        red[0][tr] = ss;
    }
    __syncthreads();
    const float inv = 1.0f / red[0][tr];

    for (int x = tg * 64; x < tg * 64 + 64; x++)
        Ab[(size_t)x * NRR + tr] *= inv;
}

// ---------------------------------------------------------------------------
// Kernel 4: out[b,r,e] = sum_x attn[b,x,r] * X[b,x,e]  (tf32 MMA, dbl-buffered)
// Tile 64r x 64e (grid 256), k-chunk 32, register-prefetch + 2 smem buffers.
// Warp layout: 2(m) x 4(n) warps; warp tile 32m x 16n.
// ---------------------------------------------------------------------------
__global__ __launch_bounds__(256) void outgemm_mma_kernel(
    const float* __restrict__ attn, const float* __restrict__ X,
    float* __restrict__ out)
{
    __shared__ unsigned As[2][32][72];   // [buf][k][r]
    __shared__ unsigned Xs[2][32][72];   // [buf][k][e]

    const int tid  = threadIdx.x;
    const int lane = tid & 31;
    const int warp = tid >> 5;
    const int wm = warp >> 2;          // 0..1  -> m offset 32*wm
    const int wn = warp & 3;           // 0..3  -> n offset 16*wn
    const int r0 = blockIdx.x * 64;
    const int e0 = blockIdx.y * 64;
    const int b  = blockIdx.z;

    const int fr = lane >> 2;
    const int fc = lane & 3;

    const float* Ab = attn + (size_t)b * NXX * NRR;
    const float* Xb = X + (size_t)b * NXX * DD;

    // load slots: each tile is 32 rows x 64 cols = 512 float4; 2 per thread
    const int lrow = tid >> 3;             // 0..31 (k row); 8 thr/row
    const int lq   = (tid & 7) << 3;       // 0..56 (2 float4)

    float c[2][2][4] = {};

    // preload chunk 0
    {
#pragma unroll
        for (int u = 0; u < 2; u++) {
            float4 va = *(const float4*)&Ab[(size_t)lrow * NRR + r0 + lq + 4*u];
            float4 vx = *(const float4*)&Xb[(size_t)lrow * DD  + e0 + lq + 4*u];
            As[0][lrow][lq + 4*u + 0] = f2tf32(va.x); As[0][lrow][lq + 4*u + 1] = f2tf32(va.y);
            As[0][lrow][lq + 4*u + 2] = f2tf32(va.z); As[0][lrow][lq + 4*u + 3] = f2tf32(va.w);
            Xs[0][lrow][lq + 4*u + 0] = f2tf32(vx.x); Xs[0][lrow][lq + 4*u + 1] = f2tf32(vx.y);
            Xs[0][lrow][lq + 4*u + 2] = f2tf32(vx.z); Xs[0][lrow][lq + 4*u + 3] = f2tf32(vx.w);
        }
    }
    __syncthreads();

    int cur = 0;
    for (int kc = 0; kc < NXX; kc += 32) {
        const int nk = kc + 32;
        float4 pa[2], px[2];
        if (nk < NXX) {
#pragma unroll
            for (int u = 0; u < 2; u++) {
                pa[u] = *(const float4*)&Ab[(size_t)(nk + lrow) * NRR + r0 + lq + 4*u];
                px[u] = *(const float4*)&Xb[(size_t)(nk + lrow) * DD  + e0 + lq + 4*u];
            }
        }

#pragma unroll
        for (int ks = 0; ks < 4; ks++) {
            const int k = ks << 3;
            unsigned a[2][4], bf[2][2];
#pragma unroll
            for (int mt = 0; mt < 2; mt++) {
                int mb = wm * 32 + mt * 16;
                a[mt][0] = As[cur][k + fc    ][mb + fr    ];
                a[mt][1] = As[cur][k + fc    ][mb + fr + 8];
                a[mt][2] = As[cur][k + fc + 4][mb + fr    ];
                a[mt][3] = As[cur][k + fc + 4][mb + fr + 8];
            }
#pragma unroll
            for (int nt = 0; nt < 2; nt++) {
                int nb = wn * 16 + nt * 8;
                bf[nt][0] = Xs[cur][k + fc    ][nb + fr];
                bf[nt][1] = Xs[cur][k + fc + 4][nb + fr];
            }
#pragma unroll
            for (int mt = 0; mt < 2; mt++)
#pragma unroll
                for (int nt = 0; nt < 2; nt++)
                    mma_tf32(c[mt][nt], a[mt], bf[nt]);
        }

        if (nk < NXX) {
            const int nxt = cur ^ 1;
#pragma unroll
            for (int u = 0; u < 2; u++) {
                As[nxt][lrow][lq + 4*u + 0] = f2tf32(pa[u].x);
                As[nxt][lrow][lq + 4*u + 1] = f2tf32(pa[u].y);
                As[nxt][lrow][lq + 4*u + 2] = f2tf32(pa[u].z);
                As[nxt][lrow][lq + 4*u + 3] = f2tf32(pa[u].w);
                Xs[nxt][lrow][lq + 4*u + 0] = f2tf32(px[u].x);
                Xs[nxt][lrow][lq + 4*u + 1] = f2tf32(px[u].y);
                Xs[nxt][lrow][lq + 4*u + 2] = f2tf32(px[u].z);
                Xs[nxt][lrow][lq + 4*u + 3] = f2tf32(px[u].w);
            }
            __syncthreads();
            cur = nxt;
        }
    }

#pragma unroll
    for (int mt = 0; mt < 2; mt++) {
        int row0 = r0 + wm * 32 + mt * 16 + fr;
#pragma unroll
        for (int nt = 0; nt < 2; nt++) {
            int col = e0 + wn * 16 + nt * 8 + 2 * fc;
            float2 o0 = {c[mt][nt][0], c[mt][nt][1]};
            float2 o1 = {c[mt][nt][2], c[mt][nt][3]};
            *(float2*)&out[((size_t)b * NRR + row0) * DD + col]     = o0;
            *(float2*)&out[((size_t)b * NRR + row0 + 8) * DD + col] = o1;
        }
    }
}

// ---------------------------------------------------------------------------
extern "C" void kernel_launch(void* const* d_in, const int* in_sizes, int n_in,
                              void* d_out, int out_size)
{
    const float* X     = (const float*)d_in[0];
    const float* ref   = (const float*)d_in[1];
    const float* W_X   = (const float*)d_in[2];
    const float* b_X   = (const float*)d_in[3];
    const float* W_ref = (const float*)d_in[4];
    const float* b_ref = (const float*)d_in[5];
    const float* v_w   = (const float*)d_in[6];
    const float* v_b   = (const float*)d_in[7];
    float* out = (float*)d_out;

    float *hX, *hR, *S, *attn;
    cudaGetSymbolAddress((void**)&hX,   g_hX);
    cudaGetSymbolAddress((void**)&hR,   g_hR);
    cudaGetSymbolAddress((void**)&S,    g_S);
    cudaGetSymbolAddress((void**)&attn, g_attn);

    // Projections (tf32 MMA, double-buffered)
    proj_mma_kernel<<<dim3(BB * NXX / 128, HH / 64, 2), 256>>>(
        X, W_X, b_X, hX, ref, W_ref, b_ref, hR);

    // Scores (f32 tanh, MUFU lane-throughput bound)
    score_kernel<<<dim3(NXX / 32, NRR / 32, BB), 256>>>(hX, hR, v_w, v_b, S);

    // Softmax over x
    softmax_kernel<<<dim3(NRR / 32, BB), 256>>>(S, attn);

    // Weighted sum: attn^T @ X per batch (tf32 MMA, double-buffered, grid 256)
    outgemm_mma_kernel<<<dim3(NRR / 64, DD / 64, BB), 256>>>(attn, X, out);
}